// round 1
// baseline (speedup 1.0000x reference)
#include <cuda_runtime.h>
#include <math.h>

// Problem constants
namespace {
constexpr int B_   = 4;
constexpr int S_   = 2048;
constexpr int HID_ = 2048;
constexpr int H_   = 16;
constexpr int KV_  = 4;
constexpr int D_   = 128;
constexpr int G_   = H_ / KV_;
constexpr float EPS_   = 1e-6f;
constexpr float SCALE_ = 0.088388347648318447f; // 128^-0.5
}

// Scratch (no cudaMalloc allowed) — ~160MB of device globals
__device__ float g_qp[(size_t)B_ * S_ * H_ * D_];   // q proj, rope'd in place  [B*S, H*D]
__device__ float g_kp[(size_t)B_ * S_ * KV_ * D_];  // k proj, rope'd in place  [B*S, KV*D]
__device__ float g_vp[(size_t)B_ * S_ * KV_ * D_];  // v proj                   [B*S, KV*D]
__device__ float g_ao[(size_t)B_ * S_ * H_ * D_];   // attention output         [B*S, H*D]

// ---------------------------------------------------------------------------
// SGEMM: C[M,N] = A[M,K] @ B[K,N], all row-major fp32.
// 128x128 tile, BK=8, 256 threads, 8x8 register tile per thread.
// M,N,K all multiples of 128/8 in this problem — no edge handling.
// ---------------------------------------------------------------------------
__global__ __launch_bounds__(256) void sgemm_kernel(
    const float* __restrict__ A, const float* __restrict__ Bw,
    float* __restrict__ C, int M, int N, int K)
{
    __shared__ float As[8][128];
    __shared__ float Bs[8][128];

    const int tid  = threadIdx.x;
    const int brow = blockIdx.y * 128;
    const int bcol = blockIdx.x * 128;
    const int tr   = tid >> 4;   // 0..15
    const int tc   = tid & 15;   // 0..15

    // load mappings
    const int a_row = tid >> 1;        // 0..127
    const int a_col = (tid & 1) * 4;   // 0 or 4
    const int b_row = tid >> 5;        // 0..7
    const int b_col = (tid & 31) * 4;  // 0..124

    float acc[8][8];
    #pragma unroll
    for (int i = 0; i < 8; i++)
        #pragma unroll
        for (int j = 0; j < 8; j++) acc[i][j] = 0.f;

    for (int k0 = 0; k0 < K; k0 += 8) {
        float4 av = *(const float4*)&A[(size_t)(brow + a_row) * K + k0 + a_col];
        float4 bv = *(const float4*)&Bw[(size_t)(k0 + b_row) * N + bcol + b_col];
        __syncthreads();
        As[a_col + 0][a_row] = av.x;
        As[a_col + 1][a_row] = av.y;
        As[a_col + 2][a_row] = av.z;
        As[a_col + 3][a_row] = av.w;
        *(float4*)&Bs[b_row][b_col] = bv;
        __syncthreads();

        #pragma unroll
        for (int kk = 0; kk < 8; kk++) {
            float4 a0 = *(const float4*)&As[kk][tr * 8];
            float4 a1 = *(const float4*)&As[kk][tr * 8 + 4];
            float4 b0 = *(const float4*)&Bs[kk][tc * 8];
            float4 b1 = *(const float4*)&Bs[kk][tc * 8 + 4];
            float a[8] = {a0.x, a0.y, a0.z, a0.w, a1.x, a1.y, a1.z, a1.w};
            float b[8] = {b0.x, b0.y, b0.z, b0.w, b1.x, b1.y, b1.z, b1.w};
            #pragma unroll
            for (int i = 0; i < 8; i++)
                #pragma unroll
                for (int j = 0; j < 8; j++)
                    acc[i][j] = fmaf(a[i], b[j], acc[i][j]);
        }
    }

    #pragma unroll
    for (int i = 0; i < 8; i++) {
        int row = brow + tr * 8 + i;
        float4 c0 = make_float4(acc[i][0], acc[i][1], acc[i][2], acc[i][3]);
        float4 c1 = make_float4(acc[i][4], acc[i][5], acc[i][6], acc[i][7]);
        *(float4*)&C[(size_t)row * N + bcol + tc * 8]     = c0;
        *(float4*)&C[(size_t)row * N + bcol + tc * 8 + 4] = c1;
    }
}

// ---------------------------------------------------------------------------
// Fused RMSNorm + RoPE, in place. One warp per (b,s,head) row of D=128.
// x layout: [B*S, nheads*D]. cos/sin: [S, D].
// ---------------------------------------------------------------------------
__global__ __launch_bounds__(256) void norm_rope_kernel(
    float* __restrict__ x, const float* __restrict__ cosb,
    const float* __restrict__ sinb, const float* __restrict__ w, int nheads)
{
    const int warp = (blockIdx.x * blockDim.x + threadIdx.x) >> 5;
    const int lane = threadIdx.x & 31;
    const int nrows = B_ * S_ * nheads;
    if (warp >= nrows) return;

    const int bs   = warp / nheads;
    const int head = warp - bs * nheads;
    const int s    = bs % S_;

    float* row = x + (size_t)bs * nheads * D_ + (size_t)head * D_;

    float x0 = row[lane];
    float x1 = row[lane + 32];
    float x2 = row[lane + 64];
    float x3 = row[lane + 96];

    float ss = x0 * x0 + x1 * x1 + x2 * x2 + x3 * x3;
    #pragma unroll
    for (int o = 16; o > 0; o >>= 1) ss += __shfl_xor_sync(0xffffffffu, ss, o);
    float inv = rsqrtf(ss * (1.0f / (float)D_) + EPS_);

    float n0 = x0 * inv * w[lane];
    float n1 = x1 * inv * w[lane + 32];
    float n2 = x2 * inv * w[lane + 64];
    float n3 = x3 * inv * w[lane + 96];

    const float* cr = cosb + (size_t)s * D_;
    const float* sr = sinb + (size_t)s * D_;

    // rotate_half: out[i] = n[i]*cos[i] - n[i+64]*sin[i]   (i < 64)
    //              out[i+64] = n[i+64]*cos[i+64] + n[i]*sin[i+64]
    row[lane]      = n0 * cr[lane]      - n2 * sr[lane];
    row[lane + 32] = n1 * cr[lane + 32] - n3 * sr[lane + 32];
    row[lane + 64] = n2 * cr[lane + 64] + n0 * sr[lane + 64];
    row[lane + 96] = n3 * cr[lane + 96] + n1 * sr[lane + 96];
}

// ---------------------------------------------------------------------------
// Flash-attention style kernel. Grid: (S/64, H, B). 256 threads.
// BM = BN = 64, D = 128. Online softmax over 32 key tiles.
// Reads g_qp/g_kp/g_vp in their projection layouts (strided rows, contiguous d).
// ---------------------------------------------------------------------------
constexpr int QSTR = 132;          // Qs/Ks/Vs row stride (128 + 4 pad)
constexpr int PSTR = 68;           // Ps row stride
constexpr int ATTN_SMEM_FLOATS = 3 * 64 * QSTR + 64 * PSTR + 3 * 64;
constexpr int ATTN_SMEM_BYTES  = ATTN_SMEM_FLOATS * 4;  // 119552

__global__ __launch_bounds__(256) void attn_kernel()
{
    extern __shared__ float sm[];
    float* Qs    = sm;                    // [64][132]
    float* Ks    = Qs + 64 * QSTR;        // [64][132]
    float* Vs    = Ks + 64 * QSTR;        // [64][132]
    float* Ps    = Vs + 64 * QSTR;        // [64][68]
    float* rmax  = Ps + 64 * PSTR;        // [64]
    float* rsum  = rmax + 64;             // [64]
    float* rcorr = rsum + 64;             // [64]

    const int tid = threadIdx.x;
    const int m0  = blockIdx.x * 64;
    const int h   = blockIdx.y;
    const int b   = blockIdx.z;
    const int kv  = h / G_;

    const float* qbase = g_qp + ((size_t)b * S_ * H_ + h) * D_;
    const float* kbase = g_kp + ((size_t)b * S_ * KV_ + kv) * D_;
    const float* vbase = g_vp + ((size_t)b * S_ * KV_ + kv) * D_;

    // Load Q tile: 64 rows x 128 cols
    #pragma unroll
    for (int it = 0; it < 8; it++) {
        int idx = tid + it * 256;
        int r   = idx >> 5;
        int c   = (idx & 31) * 4;
        float4 v = *(const float4*)&qbase[(size_t)(m0 + r) * H_ * D_ + c];
        *(float4*)&Qs[r * QSTR + c] = v;
    }
    if (tid < 64) { rmax[tid] = -3.0e38f; rsum[tid] = 0.f; }

    const int tr = tid >> 4;   // 0..15 -> 4 rows each
    const int tc = tid & 15;   // 0..15 -> (S: 4 cols) (O: 8 cols)

    float o[4][8];
    #pragma unroll
    for (int i = 0; i < 4; i++)
        #pragma unroll
        for (int j = 0; j < 8; j++) o[i][j] = 0.f;

    for (int t0 = 0; t0 < S_; t0 += 64) {
        __syncthreads();  // protect Ks/Vs/Ps from previous iteration consumers
        #pragma unroll
        for (int it = 0; it < 8; it++) {
            int idx = tid + it * 256;
            int r   = idx >> 5;
            int c   = (idx & 31) * 4;
            *(float4*)&Ks[r * QSTR + c] =
                *(const float4*)&kbase[(size_t)(t0 + r) * KV_ * D_ + c];
            *(float4*)&Vs[r * QSTR + c] =
                *(const float4*)&vbase[(size_t)(t0 + r) * KV_ * D_ + c];
        }
        __syncthreads();

        // S = Q @ K^T (64x64 tile, 4x4 per thread)
        float sacc[4][4];
        #pragma unroll
        for (int i = 0; i < 4; i++)
            #pragma unroll
            for (int j = 0; j < 4; j++) sacc[i][j] = 0.f;

        for (int d = 0; d < D_; d += 4) {
            float4 qv[4], kv4[4];
            #pragma unroll
            for (int i = 0; i < 4; i++)
                qv[i] = *(const float4*)&Qs[(tr * 4 + i) * QSTR + d];
            #pragma unroll
            for (int j = 0; j < 4; j++)
                kv4[j] = *(const float4*)&Ks[(tc * 4 + j) * QSTR + d];
            #pragma unroll
            for (int i = 0; i < 4; i++)
                #pragma unroll
                for (int j = 0; j < 4; j++) {
                    sacc[i][j] = fmaf(qv[i].x, kv4[j].x, sacc[i][j]);
                    sacc[i][j] = fmaf(qv[i].y, kv4[j].y, sacc[i][j]);
                    sacc[i][j] = fmaf(qv[i].z, kv4[j].z, sacc[i][j]);
                    sacc[i][j] = fmaf(qv[i].w, kv4[j].w, sacc[i][j]);
                }
        }
        #pragma unroll
        for (int i = 0; i < 4; i++)
            #pragma unroll
            for (int j = 0; j < 4; j++)
                Ps[(tr * 4 + i) * PSTR + tc * 4 + j] = sacc[i][j] * SCALE_;
        __syncthreads();

        // Online softmax row update (one thread per row)
        if (tid < 64) {
            float* pr = &Ps[tid * PSTR];
            float mo = rmax[tid];
            float mn = mo;
            #pragma unroll
            for (int j = 0; j < 64; j++) mn = fmaxf(mn, pr[j]);
            float corr = __expf(mo - mn);
            float s = rsum[tid] * corr;
            #pragma unroll
            for (int j = 0; j < 64; j++) {
                float p = __expf(pr[j] - mn);
                pr[j] = p;
                s += p;
            }
            rmax[tid]  = mn;
            rsum[tid]  = s;
            rcorr[tid] = corr;
        }
        __syncthreads();

        // Rescale accumulators, then O += P @ V  (4x8 per thread)
        #pragma unroll
        for (int i = 0; i < 4; i++) {
            float c = rcorr[tr * 4 + i];
            #pragma unroll
            for (int j = 0; j < 8; j++) o[i][j] *= c;
        }
        for (int kk = 0; kk < 64; kk++) {
            float4 v0 = *(const float4*)&Vs[kk * QSTR + tc * 8];
            float4 v1 = *(const float4*)&Vs[kk * QSTR + tc * 8 + 4];
            #pragma unroll
            for (int i = 0; i < 4; i++) {
                float p = Ps[(tr * 4 + i) * PSTR + kk];
                o[i][0] = fmaf(p, v0.x, o[i][0]);
                o[i][1] = fmaf(p, v0.y, o[i][1]);
                o[i][2] = fmaf(p, v0.z, o[i][2]);
                o[i][3] = fmaf(p, v0.w, o[i][3]);
                o[i][4] = fmaf(p, v1.x, o[i][4]);
                o[i][5] = fmaf(p, v1.y, o[i][5]);
                o[i][6] = fmaf(p, v1.z, o[i][6]);
                o[i][7] = fmaf(p, v1.w, o[i][7]);
            }
        }
    }

    // Normalize and write out: [B*S, H*D] layout
    float* obase = g_ao + ((size_t)b * S_ * H_ + h) * D_;
    #pragma unroll
    for (int i = 0; i < 4; i++) {
        int r = tr * 4 + i;
        float inv = 1.0f / rsum[r];
        float4 c0 = make_float4(o[i][0] * inv, o[i][1] * inv, o[i][2] * inv, o[i][3] * inv);
        float4 c1 = make_float4(o[i][4] * inv, o[i][5] * inv, o[i][6] * inv, o[i][7] * inv);
        *(float4*)&obase[(size_t)(m0 + r) * H_ * D_ + tc * 8]     = c0;
        *(float4*)&obase[(size_t)(m0 + r) * H_ * D_ + tc * 8 + 4] = c1;
    }
}

// ---------------------------------------------------------------------------
// Launch
// ---------------------------------------------------------------------------
extern "C" void kernel_launch(void* const* d_in, const int* in_sizes, int n_in,
                              void* d_out, int out_size)
{
    const float* x    = (const float*)d_in[0];  // hidden_states [B,S,HID]
    const float* cosb = (const float*)d_in[1];  // [S,D]
    const float* sinb = (const float*)d_in[2];  // [S,D]
    const float* Wq   = (const float*)d_in[3];  // [HID, H*D]
    const float* Wk   = (const float*)d_in[4];  // [HID, KV*D]
    const float* Wv   = (const float*)d_in[5];  // [HID, KV*D]
    const float* Wo   = (const float*)d_in[6];  // [H*D, HID]
    const float* qw   = (const float*)d_in[7];  // [D]
    const float* kw   = (const float*)d_in[8];  // [D]
    float* out = (float*)d_out;

    float *qp, *kp, *vp, *ao;
    cudaGetSymbolAddress((void**)&qp, g_qp);
    cudaGetSymbolAddress((void**)&kp, g_kp);
    cudaGetSymbolAddress((void**)&vp, g_vp);
    cudaGetSymbolAddress((void**)&ao, g_ao);

    const int M = B_ * S_;  // 8192

    // Projections
    sgemm_kernel<<<dim3((H_ * D_) / 128, M / 128), 256>>>(x, Wq, qp, M, H_ * D_, HID_);
    sgemm_kernel<<<dim3((KV_ * D_) / 128, M / 128), 256>>>(x, Wk, kp, M, KV_ * D_, HID_);
    sgemm_kernel<<<dim3((KV_ * D_) / 128, M / 128), 256>>>(x, Wv, vp, M, KV_ * D_, HID_);

    // RMSNorm + RoPE (in place)
    norm_rope_kernel<<<(B_ * S_ * H_) / 8, 256>>>(qp, cosb, sinb, qw, H_);
    norm_rope_kernel<<<(B_ * S_ * KV_) / 8, 256>>>(kp, cosb, sinb, kw, KV_);

    // Attention
    cudaFuncSetAttribute(attn_kernel, cudaFuncAttributeMaxDynamicSharedMemorySize,
                         ATTN_SMEM_BYTES);
    attn_kernel<<<dim3(S_ / 64, H_, B_), 256, ATTN_SMEM_BYTES>>>();

    // Output projection -> d_out
    sgemm_kernel<<<dim3(HID_ / 128, M / 128), 256>>>(ao, Wo, out, M, HID_, H_ * D_);
}

// round 3
// speedup vs baseline: 2.9009x; 2.9009x over previous
#include <cuda_runtime.h>
#include <cuda_bf16.h>
#include <cstdint>
#include <math.h>

// Problem constants
namespace {
constexpr int B_   = 4;
constexpr int S_   = 2048;
constexpr int HID_ = 2048;
constexpr int H_   = 16;
constexpr int KV_  = 4;
constexpr int D_   = 128;
constexpr int G_   = H_ / KV_;
constexpr float EPS_   = 1e-6f;
constexpr float SCALE_ = 0.088388347648318447f; // 128^-0.5
constexpr int GEMM_K = 2048;
}

// ---------------------------------------------------------------------------
// Scratch — device globals (no cudaMalloc allowed)
// ---------------------------------------------------------------------------
__device__ float g_qp[(size_t)B_ * S_ * H_ * D_];   // q proj fp32
__device__ float g_kp[(size_t)B_ * S_ * KV_ * D_];  // k proj fp32
__device__ float g_vp[(size_t)B_ * S_ * KV_ * D_];  // v proj fp32
__device__ float g_ao[(size_t)B_ * S_ * H_ * D_];   // attention out fp32

__device__ __nv_bfloat16 g_Ahi[(size_t)B_ * S_ * HID_];
__device__ __nv_bfloat16 g_Alo[(size_t)B_ * S_ * HID_];
__device__ __nv_bfloat16 g_WqT_hi[(size_t)H_ * D_ * HID_];
__device__ __nv_bfloat16 g_WqT_lo[(size_t)H_ * D_ * HID_];
__device__ __nv_bfloat16 g_WkT_hi[(size_t)KV_ * D_ * HID_];
__device__ __nv_bfloat16 g_WkT_lo[(size_t)KV_ * D_ * HID_];
__device__ __nv_bfloat16 g_WvT_hi[(size_t)KV_ * D_ * HID_];
__device__ __nv_bfloat16 g_WvT_lo[(size_t)KV_ * D_ * HID_];
__device__ __nv_bfloat16 g_WoT_hi[(size_t)HID_ * H_ * D_];
__device__ __nv_bfloat16 g_WoT_lo[(size_t)HID_ * H_ * D_];

// post norm+rope q/k as bf16 hi/lo, same layouts as fp32 versions
__device__ __nv_bfloat16 g_qhi[(size_t)B_ * S_ * H_ * D_];
__device__ __nv_bfloat16 g_qlo[(size_t)B_ * S_ * H_ * D_];
__device__ __nv_bfloat16 g_khi[(size_t)B_ * S_ * KV_ * D_];
__device__ __nv_bfloat16 g_klo[(size_t)B_ * S_ * KV_ * D_];
// V transposed: [b][kv][d][s]
__device__ __nv_bfloat16 g_vthi[(size_t)B_ * KV_ * D_ * S_];
__device__ __nv_bfloat16 g_vtlo[(size_t)B_ * KV_ * D_ * S_];

// ---------------------------------------------------------------------------
// Warp MMA helper: D = A(16x16) @ B(16x8) + D, bf16 in, fp32 accum
// ---------------------------------------------------------------------------
__device__ __forceinline__ void mma_bf16(float* c, const uint32_t* a,
                                         uint32_t b0, uint32_t b1) {
    asm volatile(
        "mma.sync.aligned.m16n8k16.row.col.f32.bf16.bf16.f32 "
        "{%0,%1,%2,%3}, {%4,%5,%6,%7}, {%8,%9}, {%0,%1,%2,%3};"
        : "+f"(c[0]), "+f"(c[1]), "+f"(c[2]), "+f"(c[3])
        : "r"(a[0]), "r"(a[1]), "r"(a[2]), "r"(a[3]), "r"(b0), "r"(b1));
}

__device__ __forceinline__ void split2(float v, __nv_bfloat16& h, __nv_bfloat16& l) {
    h = __float2bfloat16(v);
    l = __float2bfloat16(v - __bfloat162float(h));
}

// ---------------------------------------------------------------------------
// Split kernels
// ---------------------------------------------------------------------------
__global__ __launch_bounds__(256) void split_kernel(
    const float* __restrict__ X, __nv_bfloat16* __restrict__ hi,
    __nv_bfloat16* __restrict__ lo, int n4)
{
    int i = blockIdx.x * blockDim.x + threadIdx.x;
    int stride = gridDim.x * blockDim.x;
    for (; i < n4; i += stride) {
        float4 v = ((const float4*)X)[i];
        __nv_bfloat16 h0, h1, h2, h3, l0, l1, l2, l3;
        split2(v.x, h0, l0); split2(v.y, h1, l1);
        split2(v.z, h2, l2); split2(v.w, h3, l3);
        ((__nv_bfloat162*)hi)[i * 2]     = __halves2bfloat162(h0, h1);
        ((__nv_bfloat162*)hi)[i * 2 + 1] = __halves2bfloat162(h2, h3);
        ((__nv_bfloat162*)lo)[i * 2]     = __halves2bfloat162(l0, l1);
        ((__nv_bfloat162*)lo)[i * 2 + 1] = __halves2bfloat162(l2, l3);
    }
}

// W[Kd, Nd] fp32 -> hiT/loT [Nd, Kd] bf16 (transposed split)
__global__ __launch_bounds__(256) void split_T_kernel(
    const float* __restrict__ W, __nv_bfloat16* __restrict__ hiT,
    __nv_bfloat16* __restrict__ loT, int Kd, int Nd)
{
    __shared__ float t[32][33];
    const int bn = blockIdx.x * 32;
    const int bk = blockIdx.y * 32;
    const int tx = threadIdx.x, ty = threadIdx.y;
    #pragma unroll
    for (int i = ty; i < 32; i += 8)
        t[i][tx] = W[(size_t)(bk + i) * Nd + bn + tx];
    __syncthreads();
    #pragma unroll
    for (int i = ty; i < 32; i += 8) {
        float v = t[tx][i];
        __nv_bfloat16 h, l;
        split2(v, h, l);
        hiT[(size_t)(bn + i) * Kd + bk + tx] = h;
        loT[(size_t)(bn + i) * Kd + bk + tx] = l;
    }
}

// V fp32 [b,s,kv,d] -> Vt hi/lo bf16 [b,kv,d,s]
__global__ __launch_bounds__(256) void vt_split_kernel()
{
    __shared__ float t[32][33];
    const int b  = blockIdx.z / KV_;
    const int kv = blockIdx.z % KV_;
    const int s0 = blockIdx.x * 32;
    const int d0 = blockIdx.y * 32;
    const int tx = threadIdx.x, ty = threadIdx.y;
    #pragma unroll
    for (int i = ty; i < 32; i += 8)
        t[i][tx] = g_vp[(((size_t)b * S_ + s0 + i) * KV_ + kv) * D_ + d0 + tx];
    __syncthreads();
    #pragma unroll
    for (int i = ty; i < 32; i += 8) {
        float v = t[tx][i];   // = V[s0+tx][d0+i]
        __nv_bfloat16 h, l;
        split2(v, h, l);
        size_t o = (((size_t)b * KV_ + kv) * D_ + d0 + i) * S_ + s0 + tx;
        g_vthi[o] = h;
        g_vtlo[o] = l;
    }
}

// ---------------------------------------------------------------------------
// mma.sync GEMM: C[M,N] = A @ B^T, A=[M,K] hi/lo, Bt=[N,K] hi/lo bf16, fp32 out.
// bf16x3 compensation. CTA 128x128, 8 warps, KC=64.
// ---------------------------------------------------------------------------
constexpr int GP = 72;  // smem pitch in bf16 elements

__global__ __launch_bounds__(256) void mm_mma_kernel(
    const __nv_bfloat16* __restrict__ Ahi, const __nv_bfloat16* __restrict__ Alo,
    const __nv_bfloat16* __restrict__ Bhi, const __nv_bfloat16* __restrict__ Blo,
    float* __restrict__ C, int M, int N, int K)
{
    __shared__ __nv_bfloat16 As[128 * GP];
    __shared__ __nv_bfloat16 Bs[128 * GP];

    const int tid  = threadIdx.x;
    const int wid  = tid >> 5;
    const int lane = tid & 31;
    const int g    = lane >> 2;
    const int t    = lane & 3;
    const int wr   = wid >> 1;   // 0..3
    const int wc   = wid & 1;    // 0..1
    const int m0 = blockIdx.y * 128;
    const int n0 = blockIdx.x * 128;

    float acc[2][8][4];
    #pragma unroll
    for (int mb = 0; mb < 2; mb++)
        #pragma unroll
        for (int nb = 0; nb < 8; nb++)
            #pragma unroll
            for (int e = 0; e < 4; e++) acc[mb][nb][e] = 0.f;

    const int cpp = K / 64;
    const int nch = 3 * cpp;

    for (int chunk = 0; chunk < nch; ++chunk) {
        const int pass = chunk / cpp;
        const int kc   = (chunk - pass * cpp) * 64;
        const __nv_bfloat16* Ap = (pass == 2) ? Alo : Ahi;
        const __nv_bfloat16* Bp = (pass == 1) ? Blo : Bhi;

        uint4 av[4], bv[4];
        #pragma unroll
        for (int i = 0; i < 4; i++) {
            int idx = tid + i * 256;
            int row = idx >> 3;
            int c   = idx & 7;
            av[i] = *(const uint4*)&Ap[(size_t)(m0 + row) * K + kc + c * 8];
            bv[i] = *(const uint4*)&Bp[(size_t)(n0 + row) * K + kc + c * 8];
        }
        __syncthreads();
        #pragma unroll
        for (int i = 0; i < 4; i++) {
            int idx = tid + i * 256;
            int row = idx >> 3;
            int c   = idx & 7;
            *(uint4*)&As[row * GP + c * 8] = av[i];
            *(uint4*)&Bs[row * GP + c * 8] = bv[i];
        }
        __syncthreads();

        #pragma unroll
        for (int ks = 0; ks < 4; ks++) {
            const int k0 = ks * 16;
            uint32_t a[2][4];
            #pragma unroll
            for (int mb = 0; mb < 2; mb++) {
                int base = 32 * wr + 16 * mb;
                a[mb][0] = *(const uint32_t*)&As[(base + g)     * GP + k0 + 2 * t];
                a[mb][1] = *(const uint32_t*)&As[(base + g + 8) * GP + k0 + 2 * t];
                a[mb][2] = *(const uint32_t*)&As[(base + g)     * GP + k0 + 2 * t + 8];
                a[mb][3] = *(const uint32_t*)&As[(base + g + 8) * GP + k0 + 2 * t + 8];
            }
            #pragma unroll
            for (int nb = 0; nb < 8; nb++) {
                int nrow = 64 * wc + 8 * nb + g;
                uint32_t b0 = *(const uint32_t*)&Bs[nrow * GP + k0 + 2 * t];
                uint32_t b1 = *(const uint32_t*)&Bs[nrow * GP + k0 + 2 * t + 8];
                mma_bf16(acc[0][nb], a[0], b0, b1);
                mma_bf16(acc[1][nb], a[1], b0, b1);
            }
        }
    }

    #pragma unroll
    for (int mb = 0; mb < 2; mb++) {
        int row0 = m0 + 32 * wr + 16 * mb + g;
        #pragma unroll
        for (int nb = 0; nb < 8; nb++) {
            int col = n0 + 64 * wc + 8 * nb + 2 * t;
            *(float2*)&C[(size_t)row0 * N + col] =
                make_float2(acc[mb][nb][0], acc[mb][nb][1]);
            *(float2*)&C[(size_t)(row0 + 8) * N + col] =
                make_float2(acc[mb][nb][2], acc[mb][nb][3]);
        }
    }
}

// ---------------------------------------------------------------------------
// Fused RMSNorm + RoPE -> bf16 hi/lo. One warp per (b,s,head) row of D=128.
// ---------------------------------------------------------------------------
__global__ __launch_bounds__(256) void norm_rope_split_kernel(
    const float* __restrict__ x, const float* __restrict__ cosb,
    const float* __restrict__ sinb, const float* __restrict__ w,
    __nv_bfloat16* __restrict__ hi, __nv_bfloat16* __restrict__ lo, int nheads)
{
    const int warp = (blockIdx.x * blockDim.x + threadIdx.x) >> 5;
    const int lane = threadIdx.x & 31;
    const int nrows = B_ * S_ * nheads;
    if (warp >= nrows) return;

    const int bs   = warp / nheads;
    const int head = warp - bs * nheads;
    const int s    = bs % S_;

    const float* row = x + (size_t)bs * nheads * D_ + (size_t)head * D_;
    size_t obase = (size_t)bs * nheads * D_ + (size_t)head * D_;

    float x0 = row[lane];
    float x1 = row[lane + 32];
    float x2 = row[lane + 64];
    float x3 = row[lane + 96];

    float ss = x0 * x0 + x1 * x1 + x2 * x2 + x3 * x3;
    #pragma unroll
    for (int o = 16; o > 0; o >>= 1) ss += __shfl_xor_sync(0xffffffffu, ss, o);
    float inv = rsqrtf(ss * (1.0f / (float)D_) + EPS_);

    float n0 = x0 * inv * w[lane];
    float n1 = x1 * inv * w[lane + 32];
    float n2 = x2 * inv * w[lane + 64];
    float n3 = x3 * inv * w[lane + 96];

    const float* cr = cosb + (size_t)s * D_;
    const float* sr = sinb + (size_t)s * D_;

    float r0 = n0 * cr[lane]      - n2 * sr[lane];
    float r1 = n1 * cr[lane + 32] - n3 * sr[lane + 32];
    float r2 = n2 * cr[lane + 64] + n0 * sr[lane + 64];
    float r3 = n3 * cr[lane + 96] + n1 * sr[lane + 96];

    __nv_bfloat16 h, l;
    split2(r0, h, l); hi[obase + lane]      = h; lo[obase + lane]      = l;
    split2(r1, h, l); hi[obase + lane + 32] = h; lo[obase + lane + 32] = l;
    split2(r2, h, l); hi[obase + lane + 64] = h; lo[obase + lane + 64] = l;
    split2(r3, h, l); hi[obase + lane + 96] = h; lo[obase + lane + 96] = l;
}

// ---------------------------------------------------------------------------
// Flash attention with mma.sync bf16x3. BM=64, BN=64, D=128, 8 warps.
// Warp (wr=wid>>1, wc=wid&1): S tile rows 16wr, cols 32wc; O rows 16wr, cols 64wc.
// ---------------------------------------------------------------------------
constexpr int APIT = 136;  // pitch for Q/K smem (d-contig)
constexpr int TPIT = 72;   // pitch for Vt/P smem (token-contig)
constexpr int QSZ  = 64 * APIT;   // 8704
constexpr int VSZ  = 128 * TPIT;  // 9216
constexpr int PSZ  = 64 * TPIT;   // 4608
constexpr int ATT_BF16 = 4 * QSZ + 2 * VSZ + 2 * PSZ;          // 62464 bf16
constexpr int ATT_SMEM = ATT_BF16 * 2 + (64 * 3 + 128 * 2) * 4; // 126720 B

__global__ __launch_bounds__(256) void attn_mma_kernel()
{
    extern __shared__ char smc[];
    __nv_bfloat16* Qh = (__nv_bfloat16*)smc;
    __nv_bfloat16* Ql = Qh + QSZ;
    __nv_bfloat16* Kh = Ql + QSZ;
    __nv_bfloat16* Kl = Kh + QSZ;
    __nv_bfloat16* Vh = Kl + QSZ;
    __nv_bfloat16* Vl = Vh + VSZ;
    __nv_bfloat16* Ph = Vl + VSZ;
    __nv_bfloat16* Pl = Ph + PSZ;
    float* rmax  = (float*)(Pl + PSZ);
    float* rsum  = rmax + 64;
    float* rcorr = rsum + 64;
    float* spm   = rcorr + 64;   // [2][64]
    float* sps   = spm + 128;    // [2][64]

    const int tid  = threadIdx.x;
    const int wid  = tid >> 5;
    const int lane = tid & 31;
    const int g    = lane >> 2;
    const int t    = lane & 3;
    const int wr   = wid >> 1;
    const int wc   = wid & 1;

    const int m0  = blockIdx.x * 64;
    const int h   = blockIdx.y;
    const int b   = blockIdx.z;
    const int kvh = h / G_;

    const int r0 = 16 * wr + g;
    const int r1 = r0 + 8;

    // stage Q hi/lo (64 rows x 256B each array)
    {
        const __nv_bfloat16* qh = g_qhi + (((size_t)b * S_ + m0) * H_ + h) * D_;
        const __nv_bfloat16* ql = g_qlo + (((size_t)b * S_ + m0) * H_ + h) * D_;
        #pragma unroll
        for (int i = 0; i < 4; i++) {
            int idx = tid + i * 256;
            int r   = idx >> 4;
            int c   = idx & 15;
            *(uint4*)&Qh[r * APIT + c * 8] = *(const uint4*)&qh[(size_t)r * H_ * D_ + c * 8];
            *(uint4*)&Ql[r * APIT + c * 8] = *(const uint4*)&ql[(size_t)r * H_ * D_ + c * 8];
        }
    }
    if (tid < 64) { rmax[tid] = -3.0e38f; rsum[tid] = 0.f; }

    float o[8][4];
    #pragma unroll
    for (int j = 0; j < 8; j++)
        #pragma unroll
        for (int e = 0; e < 4; e++) o[j][e] = 0.f;

    const __nv_bfloat16* khb = g_khi + ((size_t)b * S_ * KV_ + kvh) * D_;
    const __nv_bfloat16* klb = g_klo + ((size_t)b * S_ * KV_ + kvh) * D_;
    const __nv_bfloat16* vhb = g_vthi + ((size_t)b * KV_ + kvh) * D_ * S_;
    const __nv_bfloat16* vlb = g_vtlo + ((size_t)b * KV_ + kvh) * D_ * S_;

    for (int t0 = 0; t0 < S_; t0 += 64) {
        __syncthreads();
        // stage K tile (64 tokens x 128 d) and Vt tile (128 d x 64 tokens)
        #pragma unroll
        for (int i = 0; i < 4; i++) {
            int idx = tid + i * 256;
            int r   = idx >> 4;
            int c   = idx & 15;
            size_t go = (size_t)(t0 + r) * KV_ * D_ + c * 8;
            *(uint4*)&Kh[r * APIT + c * 8] = *(const uint4*)&khb[go];
            *(uint4*)&Kl[r * APIT + c * 8] = *(const uint4*)&klb[go];
            int d  = idx >> 3;
            int c2 = idx & 7;
            size_t gv = (size_t)d * S_ + t0 + c2 * 8;
            *(uint4*)&Vh[d * TPIT + c2 * 8] = *(const uint4*)&vhb[gv];
            *(uint4*)&Vl[d * TPIT + c2 * 8] = *(const uint4*)&vlb[gv];
        }
        __syncthreads();

        // ---- S = Q @ K^T (bf16x3) ----
        float sacc[4][4];
        #pragma unroll
        for (int j = 0; j < 4; j++)
            #pragma unroll
            for (int e = 0; e < 4; e++) sacc[j][e] = 0.f;

        #pragma unroll
        for (int pass = 0; pass < 3; pass++) {
            const __nv_bfloat16* Aq = (pass == 2) ? Ql : Qh;
            const __nv_bfloat16* Bk = (pass == 1) ? Kl : Kh;
            #pragma unroll
            for (int ks = 0; ks < 8; ks++) {
                const int k0 = ks * 16;
                uint32_t a[4];
                a[0] = *(const uint32_t*)&Aq[r0 * APIT + k0 + 2 * t];
                a[1] = *(const uint32_t*)&Aq[r1 * APIT + k0 + 2 * t];
                a[2] = *(const uint32_t*)&Aq[r0 * APIT + k0 + 2 * t + 8];
                a[3] = *(const uint32_t*)&Aq[r1 * APIT + k0 + 2 * t + 8];
                #pragma unroll
                for (int j = 0; j < 4; j++) {
                    int nrow = 32 * wc + 8 * j + g;
                    uint32_t b0 = *(const uint32_t*)&Bk[nrow * APIT + k0 + 2 * t];
                    uint32_t b1 = *(const uint32_t*)&Bk[nrow * APIT + k0 + 2 * t + 8];
                    mma_bf16(sacc[j], a, b0, b1);
                }
            }
        }

        // ---- online softmax ----
        float mx0 = -3.0e38f, mx1 = -3.0e38f;
        #pragma unroll
        for (int j = 0; j < 4; j++) {
            #pragma unroll
            for (int e = 0; e < 4; e++) sacc[j][e] *= SCALE_;
            mx0 = fmaxf(mx0, fmaxf(sacc[j][0], sacc[j][1]));
            mx1 = fmaxf(mx1, fmaxf(sacc[j][2], sacc[j][3]));
        }
        mx0 = fmaxf(mx0, __shfl_xor_sync(0xffffffffu, mx0, 1));
        mx0 = fmaxf(mx0, __shfl_xor_sync(0xffffffffu, mx0, 2));
        mx1 = fmaxf(mx1, __shfl_xor_sync(0xffffffffu, mx1, 1));
        mx1 = fmaxf(mx1, __shfl_xor_sync(0xffffffffu, mx1, 2));
        if (t == 0) {
            spm[wc * 64 + r0] = mx0;
            spm[wc * 64 + r1] = mx1;
        }
        __syncthreads();

        float m0n = fmaxf(rmax[r0], fmaxf(spm[r0], spm[64 + r0]));
        float m1n = fmaxf(rmax[r1], fmaxf(spm[r1], spm[64 + r1]));

        float sum0 = 0.f, sum1 = 0.f;
        #pragma unroll
        for (int j = 0; j < 4; j++) {
            float p0 = __expf(sacc[j][0] - m0n);
            float p1 = __expf(sacc[j][1] - m0n);
            float p2 = __expf(sacc[j][2] - m1n);
            float p3 = __expf(sacc[j][3] - m1n);
            sum0 += p0 + p1;
            sum1 += p2 + p3;
            int col = 32 * wc + 8 * j + 2 * t;
            __nv_bfloat16 h0, h1, l0, l1;
            split2(p0, h0, l0); split2(p1, h1, l1);
            *(__nv_bfloat162*)&Ph[r0 * TPIT + col] = __halves2bfloat162(h0, h1);
            *(__nv_bfloat162*)&Pl[r0 * TPIT + col] = __halves2bfloat162(l0, l1);
            split2(p2, h0, l0); split2(p3, h1, l1);
            *(__nv_bfloat162*)&Ph[r1 * TPIT + col] = __halves2bfloat162(h0, h1);
            *(__nv_bfloat162*)&Pl[r1 * TPIT + col] = __halves2bfloat162(l0, l1);
        }
        sum0 += __shfl_xor_sync(0xffffffffu, sum0, 1);
        sum0 += __shfl_xor_sync(0xffffffffu, sum0, 2);
        sum1 += __shfl_xor_sync(0xffffffffu, sum1, 1);
        sum1 += __shfl_xor_sync(0xffffffffu, sum1, 2);
        if (t == 0) {
            sps[wc * 64 + r0] = sum0;
            sps[wc * 64 + r1] = sum1;
        }
        __syncthreads();

        if (tid < 64) {
            float mo = rmax[tid];
            float mn = fmaxf(mo, fmaxf(spm[tid], spm[64 + tid]));
            float corr = __expf(mo - mn);
            rsum[tid]  = rsum[tid] * corr + sps[tid] + sps[64 + tid];
            rmax[tid]  = mn;
            rcorr[tid] = corr;
        }
        __syncthreads();

        // rescale O accumulators
        float c0 = rcorr[r0], c1 = rcorr[r1];
        #pragma unroll
        for (int j = 0; j < 8; j++) {
            o[j][0] *= c0; o[j][1] *= c0;
            o[j][2] *= c1; o[j][3] *= c1;
        }

        // ---- O += P @ V (bf16x3) ----
        #pragma unroll
        for (int pass = 0; pass < 3; pass++) {
            const __nv_bfloat16* Pa = (pass == 2) ? Pl : Ph;
            const __nv_bfloat16* Vb = (pass == 1) ? Vl : Vh;
            #pragma unroll
            for (int ks = 0; ks < 4; ks++) {
                const int k0 = ks * 16;
                uint32_t a[4];
                a[0] = *(const uint32_t*)&Pa[r0 * TPIT + k0 + 2 * t];
                a[1] = *(const uint32_t*)&Pa[r1 * TPIT + k0 + 2 * t];
                a[2] = *(const uint32_t*)&Pa[r0 * TPIT + k0 + 2 * t + 8];
                a[3] = *(const uint32_t*)&Pa[r1 * TPIT + k0 + 2 * t + 8];
                #pragma unroll
                for (int j = 0; j < 8; j++) {
                    int nrow = 64 * wc + 8 * j + g;
                    uint32_t b0 = *(const uint32_t*)&Vb[nrow * TPIT + k0 + 2 * t];
                    uint32_t b1 = *(const uint32_t*)&Vb[nrow * TPIT + k0 + 2 * t + 8];
                    mma_bf16(o[j], a, b0, b1);
                }
            }
        }
    }

    // epilogue
    float inv0 = 1.0f / rsum[r0];
    float inv1 = 1.0f / rsum[r1];
    size_t row0 = ((size_t)b * S_ + m0 + r0) * H_ * D_;
    size_t row1 = ((size_t)b * S_ + m0 + r1) * H_ * D_;
    #pragma unroll
    for (int j = 0; j < 8; j++) {
        int col = h * D_ + 64 * wc + 8 * j + 2 * t;
        *(float2*)&g_ao[row0 + col] = make_float2(o[j][0] * inv0, o[j][1] * inv0);
        *(float2*)&g_ao[row1 + col] = make_float2(o[j][2] * inv1, o[j][3] * inv1);
    }
}

// ---------------------------------------------------------------------------
// Launch
// ---------------------------------------------------------------------------
extern "C" void kernel_launch(void* const* d_in, const int* in_sizes, int n_in,
                              void* d_out, int out_size)
{
    const float* x    = (const float*)d_in[0];
    const float* cosb = (const float*)d_in[1];
    const float* sinb = (const float*)d_in[2];
    const float* Wq   = (const float*)d_in[3];
    const float* Wk   = (const float*)d_in[4];
    const float* Wv   = (const float*)d_in[5];
    const float* Wo   = (const float*)d_in[6];
    const float* qw   = (const float*)d_in[7];
    const float* kw   = (const float*)d_in[8];
    float* out = (float*)d_out;

    float *qp, *kp, *vp, *ao;
    cudaGetSymbolAddress((void**)&qp, g_qp);
    cudaGetSymbolAddress((void**)&kp, g_kp);
    cudaGetSymbolAddress((void**)&vp, g_vp);
    cudaGetSymbolAddress((void**)&ao, g_ao);
    __nv_bfloat16 *Ahi, *Alo, *WqTh, *WqTl, *WkTh, *WkTl, *WvTh, *WvTl, *WoTh, *WoTl;
    __nv_bfloat16 *qhi, *qlo, *khi, *klo;
    cudaGetSymbolAddress((void**)&Ahi,  g_Ahi);
    cudaGetSymbolAddress((void**)&Alo,  g_Alo);
    cudaGetSymbolAddress((void**)&WqTh, g_WqT_hi);
    cudaGetSymbolAddress((void**)&WqTl, g_WqT_lo);
    cudaGetSymbolAddress((void**)&WkTh, g_WkT_hi);
    cudaGetSymbolAddress((void**)&WkTl, g_WkT_lo);
    cudaGetSymbolAddress((void**)&WvTh, g_WvT_hi);
    cudaGetSymbolAddress((void**)&WvTl, g_WvT_lo);
    cudaGetSymbolAddress((void**)&WoTh, g_WoT_hi);
    cudaGetSymbolAddress((void**)&WoTl, g_WoT_lo);
    cudaGetSymbolAddress((void**)&qhi,  g_qhi);
    cudaGetSymbolAddress((void**)&qlo,  g_qlo);
    cudaGetSymbolAddress((void**)&khi,  g_khi);
    cudaGetSymbolAddress((void**)&klo,  g_klo);

    const int M = B_ * S_;                 // 8192
    const int n4x = M * HID_ / 4;

    cudaFuncSetAttribute(attn_mma_kernel,
                         cudaFuncAttributeMaxDynamicSharedMemorySize, ATT_SMEM);

    // Split inputs + weights
    split_kernel<<<4096, 256>>>(x, Ahi, Alo, n4x);
    split_T_kernel<<<dim3((H_ * D_) / 32, HID_ / 32), dim3(32, 8)>>>(Wq, WqTh, WqTl, HID_, H_ * D_);
    split_T_kernel<<<dim3((KV_ * D_) / 32, HID_ / 32), dim3(32, 8)>>>(Wk, WkTh, WkTl, HID_, KV_ * D_);
    split_T_kernel<<<dim3((KV_ * D_) / 32, HID_ / 32), dim3(32, 8)>>>(Wv, WvTh, WvTl, HID_, KV_ * D_);
    split_T_kernel<<<dim3(HID_ / 32, (H_ * D_) / 32), dim3(32, 8)>>>(Wo, WoTh, WoTl, H_ * D_, HID_);

    // Projections (tensor cores, bf16x3)
    mm_mma_kernel<<<dim3((H_ * D_) / 128, M / 128), 256>>>(Ahi, Alo, WqTh, WqTl, qp, M, H_ * D_, GEMM_K);
    mm_mma_kernel<<<dim3((KV_ * D_) / 128, M / 128), 256>>>(Ahi, Alo, WkTh, WkTl, kp, M, KV_ * D_, GEMM_K);
    mm_mma_kernel<<<dim3((KV_ * D_) / 128, M / 128), 256>>>(Ahi, Alo, WvTh, WvTl, vp, M, KV_ * D_, GEMM_K);

    // RMSNorm + RoPE -> bf16 hi/lo
    norm_rope_split_kernel<<<(B_ * S_ * H_) / 8, 256>>>(qp, cosb, sinb, qw, qhi, qlo, H_);
    norm_rope_split_kernel<<<(B_ * S_ * KV_) / 8, 256>>>(kp, cosb, sinb, kw, khi, klo, KV_);

    // V transpose + split
    vt_split_kernel<<<dim3(S_ / 32, D_ / 32, B_ * KV_), dim3(32, 8)>>>();

    // Attention (tensor cores, bf16x3)
    attn_mma_kernel<<<dim3(S_ / 64, H_, B_), 256, ATT_SMEM>>>();

    // Output projection
    split_kernel<<<4096, 256>>>(ao, Ahi, Alo, n4x);
    mm_mma_kernel<<<dim3(HID_ / 128, M / 128), 256>>>(Ahi, Alo, WoTh, WoTl, out, M, HID_, GEMM_K);
}